// round 10
// baseline (speedup 1.0000x reference)
#include <cuda_runtime.h>
#include <cuda_fp16.h>
#include <math.h>
#include <stdint.h>

#define N_NODES 100000
#define N_EDGES 1600000
#define IN_F 64
#define HID_F 64
#define OUT_F 16

#define SCAN_B 1024
#define MAX_SCAN_BLKS 128

// ---- scratch (static __device__ globals; zero-initialized) ----
__device__ __align__(16) int    g_cnt[N_NODES];     // in-degree (zeroed by last kernel)
__device__ __align__(16) int    g_row[N_NODES];     // CSR exclusive offsets (begin)
__device__ __align__(16) int    g_rank[N_EDGES];    // edge rank within dst bucket
__device__ __align__(16) int    g_blksum[MAX_SCAN_BLKS];
__device__ int g_bar1, g_bar2;                      // spin barriers (reset each replay)
__device__ __align__(16) float  g_dis[N_NODES];     // rsqrt(deg+1); L2-resident 400KB
__device__ __align__(16) int    g_csr[N_EDGES];     // src only
__device__ __align__(16) __half g_h1[(size_t)N_NODES * HID_F];  // x@W1 (unscaled, fp16)
__device__ __align__(16) float  g_agg1[(size_t)N_NODES * HID_F];
__device__ __align__(16) __half g_h2[(size_t)N_NODES * OUT_F];  // layer-2 msgs (fp16)

// inline dtype detect: int64 node ids < 2^31 have zero odd 32-bit words
__device__ __forceinline__ int edge_stride(const int* __restrict__ ei32, int E) {
    int is64 = 1;
    int n = E < 16 ? E : 16;
#pragma unroll
    for (int i = 0; i < 16; i++)
        if (i < n && ei32[2 * i + 1] != 0) is64 = 0;
    return is64 ? 2 : 1;
}

// ---------------------------------------------------------------------------
// GEMM1: h1 = x @ W1, fp16 out, unscaled. 128x64 block tile, 4x8 thread tile.
__global__ __launch_bounds__(256) void gemm1_kernel(
    const float* __restrict__ x, const float* __restrict__ W1, int N) {
    __shared__ float Wsh[IN_F][HID_F];   // 16KB
    __shared__ float Xsh[16][128];       // 8KB per k-chunk (transposed)

    int tid = threadIdx.x;
    int tx = tid & 7;
    int ty = tid >> 3;
    int nb = blockIdx.x * 128;

    for (int i = tid; i < 1024; i += 256) {
        int row = i >> 4, c4 = (i & 15) << 2;
        *reinterpret_cast<float4*>(&Wsh[row][c4]) =
            *reinterpret_cast<const float4*>(&W1[row * HID_F + c4]);
    }

    float acc[4][8];
#pragma unroll
    for (int i = 0; i < 4; i++)
#pragma unroll
        for (int j = 0; j < 8; j++) acc[i][j] = 0.0f;

    for (int kc = 0; kc < 4; kc++) {
        int k0 = kc * 16;
        __syncthreads();
        for (int i = tid; i < 512; i += 256) {
            int node = i >> 2, k4 = (i & 3) << 2;
            float4 v = make_float4(0.f, 0.f, 0.f, 0.f);
            int n = nb + node;
            if (n < N)
                v = *reinterpret_cast<const float4*>(&x[(size_t)n * IN_F + k0 + k4]);
            Xsh[k4 + 0][node] = v.x;
            Xsh[k4 + 1][node] = v.y;
            Xsh[k4 + 2][node] = v.z;
            Xsh[k4 + 3][node] = v.w;
        }
        __syncthreads();
#pragma unroll
        for (int k = 0; k < 16; k++) {
            float4 xv = *reinterpret_cast<const float4*>(&Xsh[k][ty * 4]);
            float4 wa = *reinterpret_cast<const float4*>(&Wsh[k0 + k][tx * 8]);
            float4 wb = *reinterpret_cast<const float4*>(&Wsh[k0 + k][tx * 8 + 4]);
            float xs[4] = {xv.x, xv.y, xv.z, xv.w};
#pragma unroll
            for (int i = 0; i < 4; i++) {
                acc[i][0] += xs[i] * wa.x;
                acc[i][1] += xs[i] * wa.y;
                acc[i][2] += xs[i] * wa.z;
                acc[i][3] += xs[i] * wa.w;
                acc[i][4] += xs[i] * wb.x;
                acc[i][5] += xs[i] * wb.y;
                acc[i][6] += xs[i] * wb.z;
                acc[i][7] += xs[i] * wb.w;
            }
        }
    }

#pragma unroll
    for (int i = 0; i < 4; i++) {
        int n = nb + ty * 4 + i;
        if (n >= N) continue;
        __align__(16) __half2 h[4];
#pragma unroll
        for (int p = 0; p < 4; p++)
            h[p] = __floats2half2_rn(acc[i][p * 2], acc[i][p * 2 + 1]);
        *reinterpret_cast<uint4*>(&g_h1[(size_t)n * HID_F + tx * 8]) =
            *reinterpret_cast<uint4*>(h);
    }
}

// degree histogram on dst; stores per-edge rank within its bucket
__global__ void build_hist_kernel(const int* __restrict__ ei32, int E) {
    int e = blockIdx.x * blockDim.x + threadIdx.x;
    if (e >= E) return;
    int stride = edge_stride(ei32, E);
    int dst = ei32[((size_t)E + e) * stride];
    g_rank[e] = atomicAdd(&g_cnt[dst], 1);
}

// ---------------------------------------------------------------------------
// Fused scan + fill: 98 blocks x 1024 threads, all co-resident (<=148 SMs),
// device-wide spin barriers are deadlock-free. Barriers reset by last kernel.
__device__ __forceinline__ void grid_bar(int* bar, int nblks) {
    __syncthreads();
    if (threadIdx.x == 0) {
        __threadfence();
        atomicAdd(bar, 1);
        while (*(volatile int*)bar < nblks) { }
    }
    __syncthreads();
}

__global__ __launch_bounds__(SCAN_B) void scan_fill_kernel(
    const int* __restrict__ ei32, int N, int E, int nblks) {
    __shared__ int wsum[32];
    __shared__ int excl_sm[1];

    int i = blockIdx.x * SCAN_B + threadIdx.x;
    int v = (i < N) ? g_cnt[i] : 0;
    int lane = threadIdx.x & 31, wid = threadIdx.x >> 5;

    // local exclusive scan (warp shuffle)
    int s = v;
#pragma unroll
    for (int o = 1; o < 32; o *= 2) {
        int t = __shfl_up_sync(0xffffffffu, s, o);
        if (lane >= o) s += t;
    }
    if (lane == 31) wsum[wid] = s;
    __syncthreads();
    if (wid == 0) {
        int w = wsum[lane];
        int ws = w;
#pragma unroll
        for (int o = 1; o < 32; o *= 2) {
            int t = __shfl_up_sync(0xffffffffu, ws, o);
            if (lane >= o) ws += t;
        }
        wsum[lane] = ws - w;
        if (lane == 31) g_blksum[blockIdx.x] = ws;   // block total
    }
    __syncthreads();
    int local_excl = wsum[wid] + s - v;

    grid_bar(&g_bar1, nblks);   // all block totals visible

    // warp 0: exclusive prefix of the preceding block totals (this block only)
    if (threadIdx.x < 32) {
        int b4 = lane * 4;
        int pre = 0;
#pragma unroll 4
        for (int q = 0; q < 4; q++) {
            int b = b4 + q;
            if (b < blockIdx.x) pre += g_blksum[b];
        }
#pragma unroll
        for (int o = 1; o < 32; o *= 2) {
            int t = __shfl_down_sync(0xffffffffu, pre, o);
            pre += t;   // full-sum via tree (result valid on lane 0)
        }
        if (lane == 0) excl_sm[0] = pre;
    }
    __syncthreads();

    if (i < N) {
        g_row[i] = local_excl + excl_sm[0];
        g_dis[i] = rsqrtf((float)(v + 1));
    }

    grid_bar(&g_bar2, nblks);   // all final offsets + dis visible

    // fill phase (atomic-free): grid-stride over edges
    int stride = edge_stride(ei32, E);
    int step = nblks * SCAN_B;
#pragma unroll 4
    for (int e = blockIdx.x * SCAN_B + threadIdx.x; e < E; e += step) {
        int src = ei32[(size_t)e * stride];
        int dst = ei32[((size_t)E + e) * stride];
        g_csr[g_row[dst] + g_rank[e]] = src;
    }
}

// ---------------------------------------------------------------------------
// gather layer 1 — WARP PER NODE (zero intra-warp divergence):
//   agg1[n] = dis[n] * ( dis[n]*h1[n] + sum_s dis[s]*h1[s] )
// lane owns 2 features (half2 = 4B of the 128B row); 8 edges per iteration.
__global__ __launch_bounds__(256) void gather1_kernel(int N) {
    int w = (blockIdx.x * blockDim.x + threadIdx.x) >> 5;
    int lane = threadIdx.x & 31;
    if (w >= N) return;
    int n = w;

    float dn = g_dis[n];
    int beg = g_row[n];
    int end = beg + g_cnt[n];

    float2 acc;
    {
        __half2 h = *reinterpret_cast<const __half2*>(&g_h1[(size_t)n * HID_F + lane * 2]);
        float2 f = __half22float2(h);
        acc.x = dn * f.x;
        acc.y = dn * f.y;
    }

    int j = beg;
    // full iterations: 8 edges each, warp-uniform trip count
    for (; j + 8 <= end; j += 8) {
        int sld = 0; float dld = 0.f;
        if (lane < 8) { sld = g_csr[j + lane]; dld = g_dis[sld]; }
#pragma unroll
        for (int p = 0; p < 8; p++) {
            int   sp = __shfl_sync(0xffffffffu, sld, p);
            float dp = __shfl_sync(0xffffffffu, dld, p);
            __half2 h = *reinterpret_cast<const __half2*>(
                &g_h1[(size_t)sp * HID_F + lane * 2]);
            float2 f = __half22float2(h);
            acc.x += dp * f.x;
            acc.y += dp * f.y;
        }
    }
    int r = end - j;
    if (r > 0) {
        int sld = 0; float dld = 0.f;
        if (lane < r) { sld = g_csr[j + lane]; dld = g_dis[sld]; }
        for (int p = 0; p < r; p++) {
            int   sp = __shfl_sync(0xffffffffu, sld, p);
            float dp = __shfl_sync(0xffffffffu, dld, p);
            __half2 h = *reinterpret_cast<const __half2*>(
                &g_h1[(size_t)sp * HID_F + lane * 2]);
            float2 f = __half22float2(h);
            acc.x += dp * f.x;
            acc.y += dp * f.y;
        }
    }

    *reinterpret_cast<float2*>(&g_agg1[(size_t)n * HID_F + lane * 2]) =
        make_float2(acc.x * dn, acc.y * dn);
}

// GEMM2: h2 = relu(agg1 + b1) @ W2, fp16 out, unscaled. 2 nodes/thread.
__global__ __launch_bounds__(256) void gemm2_kernel(
    const float* __restrict__ W2, const float* __restrict__ b1, int N) {
    __shared__ float Wsh[HID_F][OUT_F];
    __shared__ float bsh[HID_F];
    for (int i = threadIdx.x; i < HID_F * OUT_F; i += blockDim.x)
        Wsh[i >> 4][i & 15] = W2[i];
    if (threadIdx.x < HID_F) bsh[threadIdx.x] = b1[threadIdx.x];
    __syncthreads();

    int t = blockIdx.x * blockDim.x + threadIdx.x;
    int n0 = t * 2, n1 = t * 2 + 1;
    if (n0 >= N) return;
    bool has1 = (n1 < N);

    float acc0[OUT_F], acc1[OUT_F];
#pragma unroll
    for (int j = 0; j < OUT_F; j++) { acc0[j] = 0.0f; acc1[j] = 0.0f; }

    const float4* a0 = reinterpret_cast<const float4*>(&g_agg1[(size_t)n0 * HID_F]);
    const float4* a1 = reinterpret_cast<const float4*>(&g_agg1[(size_t)n1 * HID_F]);

#pragma unroll 4
    for (int k4 = 0; k4 < HID_F / 4; k4++) {
        float4 v0 = a0[k4];
        float4 v1 = has1 ? a1[k4] : make_float4(0.f, 0.f, 0.f, 0.f);
        float h0s[4] = {v0.x, v0.y, v0.z, v0.w};
        float h1s[4] = {v1.x, v1.y, v1.z, v1.w};
#pragma unroll
        for (int kk = 0; kk < 4; kk++) {
            int k = k4 * 4 + kk;
            float bb = bsh[k];
            float h0 = fmaxf(h0s[kk] + bb, 0.0f);
            float h1 = fmaxf(h1s[kk] + bb, 0.0f);
#pragma unroll
            for (int j4 = 0; j4 < OUT_F / 4; j4++) {
                float4 w = *reinterpret_cast<const float4*>(&Wsh[k][j4 * 4]);
                acc0[j4 * 4 + 0] += h0 * w.x;  acc1[j4 * 4 + 0] += h1 * w.x;
                acc0[j4 * 4 + 1] += h0 * w.y;  acc1[j4 * 4 + 1] += h1 * w.y;
                acc0[j4 * 4 + 2] += h0 * w.z;  acc1[j4 * 4 + 2] += h1 * w.z;
                acc0[j4 * 4 + 3] += h0 * w.w;  acc1[j4 * 4 + 3] += h1 * w.w;
            }
        }
    }

    {
        __align__(16) __half2 h[8];
#pragma unroll
        for (int p = 0; p < 8; p++)
            h[p] = __floats2half2_rn(acc0[p * 2], acc0[p * 2 + 1]);
        *reinterpret_cast<uint4*>(&g_h2[(size_t)n0 * OUT_F]) =
            *reinterpret_cast<uint4*>(&h[0]);
        *reinterpret_cast<uint4*>(&g_h2[(size_t)n0 * OUT_F + 8]) =
            *reinterpret_cast<uint4*>(&h[4]);
    }
    if (has1) {
        __align__(16) __half2 h[8];
#pragma unroll
        for (int p = 0; p < 8; p++)
            h[p] = __floats2half2_rn(acc1[p * 2], acc1[p * 2 + 1]);
        *reinterpret_cast<uint4*>(&g_h2[(size_t)n1 * OUT_F]) =
            *reinterpret_cast<uint4*>(&h[0]);
        *reinterpret_cast<uint4*>(&g_h2[(size_t)n1 * OUT_F + 8]) =
            *reinterpret_cast<uint4*>(&h[4]);
    }
}

// gather layer 2 + log_softmax fused — 8 lanes/node, 2 feats (half2) each,
// 8 edges/iter. Resets g_cnt and spin barriers for next replay.
__global__ __launch_bounds__(256) void gather2_lsm_kernel(
    const float* __restrict__ b2, float* __restrict__ out, int N) {
    int t = blockIdx.x * blockDim.x + threadIdx.x;
    int n = t >> 3;
    int c = t & 7;
    if (n >= N) return;

    unsigned lane = threadIdx.x & 31;
    unsigned gmask = 0xffu << (lane & ~7u);

    float dn = g_dis[n];
    int beg = g_row[n];
    int end = beg + g_cnt[n];

    float2 acc;
    {
        __half2 h = *reinterpret_cast<const __half2*>(&g_h2[(size_t)n * OUT_F + c * 2]);
        float2 f = __half22float2(h);
        acc.x = dn * f.x;
        acc.y = dn * f.y;
    }

    int j = beg;
    for (; j + 8 <= end; j += 8) {
        int sld = g_csr[j + c];
        float dld = g_dis[sld];
#pragma unroll
        for (int p = 0; p < 8; p++) {
            int   sp = __shfl_sync(gmask, sld, p, 8);
            float dp = __shfl_sync(gmask, dld, p, 8);
            __half2 h = *reinterpret_cast<const __half2*>(
                &g_h2[(size_t)sp * OUT_F + c * 2]);
            float2 f = __half22float2(h);
            acc.x += dp * f.x;
            acc.y += dp * f.y;
        }
    }
    int r = end - j;
    if (r > 0) {
        int sld = 0; float dld = 0.f;
        if (c < r) { sld = g_csr[j + c]; dld = g_dis[sld]; }
        for (int p = 0; p < r; p++) {
            int   sp = __shfl_sync(gmask, sld, p, 8);
            float dp = __shfl_sync(gmask, dld, p, 8);
            __half2 h = *reinterpret_cast<const __half2*>(
                &g_h2[(size_t)sp * OUT_F + c * 2]);
            float2 f = __half22float2(h);
            acc.x += dp * f.x;
            acc.y += dp * f.y;
        }
    }

    float2 bb = *reinterpret_cast<const float2*>(&b2[c * 2]);
    float v0 = acc.x * dn + bb.x;
    float v1 = acc.y * dn + bb.y;

    // log_softmax over 16 values spread as 2 per lane across 8 lanes
    float mx = fmaxf(v0, v1);
    mx = fmaxf(mx, __shfl_xor_sync(gmask, mx, 1, 8));
    mx = fmaxf(mx, __shfl_xor_sync(gmask, mx, 2, 8));
    mx = fmaxf(mx, __shfl_xor_sync(gmask, mx, 4, 8));
    float s = __expf(v0 - mx) + __expf(v1 - mx);
    s += __shfl_xor_sync(gmask, s, 1, 8);
    s += __shfl_xor_sync(gmask, s, 2, 8);
    s += __shfl_xor_sync(gmask, s, 4, 8);
    float ls = mx + logf(s);

    *reinterpret_cast<float2*>(&out[(size_t)n * OUT_F + c * 2]) =
        make_float2(v0 - ls, v1 - ls);

    if (c == 0) g_cnt[n] = 0;
    if (n == 0 && c == 1) { g_bar1 = 0; g_bar2 = 0; }
}

// ---------------------------------------------------------------------------
extern "C" void kernel_launch(void* const* d_in, const int* in_sizes, int n_in,
                              void* d_out, int out_size) {
    const float* x    = (const float*)d_in[0];
    const int*   ei32 = (const int*)d_in[1];
    const float* W1   = (const float*)d_in[2];
    const float* b1   = (const float*)d_in[3];
    const float* W2   = (const float*)d_in[4];
    const float* b2   = (const float*)d_in[5];
    float* out = (float*)d_out;

    int N = in_sizes[0] / IN_F;
    int E = in_sizes[1] / 2;

    const int T = 256;
    int gE = (E + T - 1) / T;
    int nScanBlks = (N + SCAN_B - 1) / SCAN_B;   // 98 <= 148 SMs -> co-resident

    static cudaStream_t s_side = 0;
    static cudaEvent_t ev_fork = 0, ev_join = 0;
    static int s_init = 0;
    if (!s_init) {
        s_init = 1;
        if (cudaStreamCreateWithFlags(&s_side, cudaStreamNonBlocking) != cudaSuccess)
            s_side = 0;
        if (s_side) {
            if (cudaEventCreateWithFlags(&ev_fork, cudaEventDisableTiming) != cudaSuccess ||
                cudaEventCreateWithFlags(&ev_join, cudaEventDisableTiming) != cudaSuccess)
                s_side = 0;
        }
    }

    if (s_side) {
        cudaEventRecord(ev_fork, 0);
        cudaStreamWaitEvent(s_side, ev_fork, 0);

        build_hist_kernel<<<gE, T, 0, s_side>>>(ei32, E);               // 1
        scan_fill_kernel<<<nScanBlks, SCAN_B, 0, s_side>>>(ei32, N, E, nScanBlks); // 2
        cudaEventRecord(ev_join, s_side);

        gemm1_kernel<<<(N + 127) / 128, 256>>>(x, W1, N);               // 3 (concurrent)
        cudaStreamWaitEvent(0, ev_join, 0);
    } else {
        gemm1_kernel<<<(N + 127) / 128, 256>>>(x, W1, N);
        build_hist_kernel<<<gE, T>>>(ei32, E);
        scan_fill_kernel<<<nScanBlks, SCAN_B>>>(ei32, N, E, nScanBlks);
    }

    gather1_kernel<<<(N * 32 + T - 1) / T, T>>>(N);                     // 4 <- profiled
    gemm2_kernel<<<((N + 1) / 2 + T - 1) / T, T>>>(W2, b1, N);          // 5
    gather2_lsm_kernel<<<(N * 8 + T - 1) / T, T>>>(b2, out, N);         // 6
}